// round 15
// baseline (speedup 1.0000x reference)
#include <cuda_runtime.h>
#include <cstdint>
#include <cstddef>
#include <math_constants.h>

// ---------------------------------------------------------------------------
// JointNet: DGCNN geo-net (3 dynamic-kNN edge convs) + weighted joint pooling
//           + skeleton edge convs (fixed one-ring) + joint MLP.
// Edge conv rewrite:  max_k leaky(w1*(xj-xi)+w2*xi+b)
//                   = leaky( Q[i] + max_k P[idx[i,k]] ),
//                     P = X*w1^T, Q = X*(w2-w1)^T + b
// R15: #pragma unroll 1 on the kNN phase loop. The unrolled body was
//      ~11KB x NPH of SASS (45KB for C=64, 90KB for C=128) -- overflowing
//      L0/L1.5/I$L2 and re-streaming instructions every tile. Rolled, the
//      body fits the instruction caches. Everything else identical to R14.
// ---------------------------------------------------------------------------

static constexpr int Bb = 4, Nn = 4096, Jj = 24, KTOP = 20;

#define LRELU(x) ((x) >= 0.f ? (x) : 0.2f * (x))

// ------------------------- scratch (floats) --------------------------------
static constexpr size_t OF_FEAT = 0;                       // [4][4096][451]
static constexpr size_t SZ_FEAT = (size_t)Bb * Nn * 451;
static constexpr size_t OF_PQ   = OF_FEAT + SZ_FEAT;       // [4*4096][512] max
static constexpr size_t SZ_PQ   = (size_t)Bb * Nn * 512;
static constexpr size_t OF_NORM = OF_PQ + SZ_PQ;           // [4*4096]
static constexpr size_t SZ_NORM = (size_t)Bb * Nn;
static constexpr size_t OF_POOL = OF_NORM + SZ_NORM;       // [96][451]
static constexpr size_t SZ_POOL = (size_t)Bb * Jj * 451;
static constexpr size_t OF_JNT  = OF_POOL + SZ_POOL;       // [96][448]
static constexpr size_t SZ_JNT  = (size_t)Bb * Jj * 448;
static constexpr size_t OF_T1   = OF_JNT + SZ_JNT;         // [96][512]
static constexpr size_t SZ_T1   = (size_t)Bb * Jj * 512;
static constexpr size_t OF_T2   = OF_T1 + SZ_T1;           // [96][256]
static constexpr size_t SZ_T2   = (size_t)Bb * Jj * 256;
static constexpr size_t OF_WG1  = OF_T2 + SZ_T2;   static constexpr size_t SZ_WG1 = 2 * 64 * 3;
static constexpr size_t OF_WG2  = OF_WG1 + SZ_WG1; static constexpr size_t SZ_WG2 = 2 * 128 * 64;
static constexpr size_t OF_WG3  = OF_WG2 + SZ_WG2; static constexpr size_t SZ_WG3 = 2 * 256 * 128;
static constexpr size_t OF_WS1  = OF_WG3 + SZ_WG3; static constexpr size_t SZ_WS1 = 2 * 256 * 451;
static constexpr size_t OF_WS2  = OF_WS1 + SZ_WS1; static constexpr size_t SZ_WS2 = 2 * 128 * 256;
static constexpr size_t OF_WS3  = OF_WS2 + SZ_WS2; static constexpr size_t SZ_WS3 = 2 * 64 * 128;
static constexpr size_t SF_TOTAL = OF_WS3 + SZ_WS3;

__device__ float d_SF[SF_TOTAL];
__device__ int   d_SI[(size_t)Bb * Nn * KTOP];

// ------------------------- f32x2 helpers (sm_10x packed fp32) --------------
__device__ __forceinline__ unsigned long long pack2s(float v) {
    unsigned long long r;
    asm("mov.b64 %0, {%1, %2};" : "=l"(r) : "f"(v), "f"(v));
    return r;
}
__device__ __forceinline__ float2 unpack2(unsigned long long v) {
    float2 r;
    asm("mov.b64 {%0, %1}, %2;" : "=f"(r.x), "=f"(r.y) : "l"(v));
    return r;
}
__device__ __forceinline__ void ffma2(unsigned long long& d,
                                      unsigned long long a, unsigned long long b) {
    asm("fma.rn.f32x2 %0, %1, %2, %0;" : "+l"(d) : "l"(a), "l"(b));
}

// ------------------------- kNN body (exact top-20) -------------------------
// 64 queries x 128-cand tiles; resident query slab; double-buffered KC=16
// candidate staging (strength-reduced addressing); query-paired f32x2
// microtile; shared-tau masks; 4 threads/query sorted top-20 + 4-way merge.
// If norms==nullptr (C==3), row norms are computed directly from X.
// Phase loop is NOT unrolled (I-cache: body must stay ~11KB).
template<int C>
__device__ __forceinline__ void knn_body(const float* __restrict__ X, int ldx,
                                         const float* __restrict__ norms,
                                         int* __restrict__ out_idx,
                                         int bx, int b, float* sm) {
    constexpr int KC = (C < 16) ? C : 16;
    constexpr int NPH = C / KC;
    constexpr int QT = 64, CT = 128;
    constexpr int CPAD = 132, QPAD = 68, DPAD = 132;
    constexpr int NC = (CT * KC + 255) / 256;
    constexpr int RSTEP = 256 / KC;

    float* qsF = sm;                      // [C][QPAD]  resident
    float* cs0 = qsF + C * QPAD;          // [KC][CPAD] buffer 0
    float* cs1 = cs0 + KC * CPAD;         // [KC][CPAD] buffer 1
    float* dt  = cs1 + KC * CPAD;         // [QT][DPAD]
    float* cn  = dt + QT * DPAD;          // [CT]
    float* qn  = cn + CT;                 // [QT]

    const int t  = threadIdx.x;
    const int tx = t & 31, ty = t >> 5;
    const int q0 = bx * QT;
    const float* Xb = X + (size_t)b * Nn * ldx;
    const float* nb = norms ? norms + (size_t)b * Nn : nullptr;

    if (t < QT) {
        if (nb) qn[t] = nb[q0 + t];
        else {
            const float* r = Xb + (size_t)(q0 + t) * ldx;
            qn[t] = r[0] * r[0] + r[1] * r[1] + r[2] * r[2];
        }
    }
    // resident query slab
    if constexpr (C >= 16) {
        constexpr int QIT = QT * C / 256;
        constexpr int QSTEP = 256 / C;
        const int qcol = t & (C - 1);
        const int qrow0 = t / C;
        float* qdst = qsF + qcol * QPAD + qrow0;
        const float* qsrc = Xb + (size_t)(q0 + qrow0) * ldx + qcol;
        const size_t qinc = (size_t)QSTEP * ldx;
        #pragma unroll 4
        for (int j = 0; j < QIT; ++j) { qdst[j * QSTEP] = *qsrc; qsrc += qinc; }
    } else {
        for (int e = t; e < QT * C; e += 256) {
            int row = e / C, col = e - row * C;
            qsF[col * QPAD + row] = Xb[(size_t)(q0 + row) * ldx + col];
        }
    }

    float ld[KTOP]; int li[KTOP];
    #pragma unroll
    for (int s = 0; s < KTOP; ++s) { ld[s] = CUDART_INF_F; li[s] = 0x7fffffff; }

    float rc[NC];
    const int kkc  = t & (KC - 1);
    const int row0 = t / KC;
    const size_t cstep = (size_t)RSTEP * ldx;

    for (int jb = 0; jb < Nn; jb += CT) {
        if (t < CT) {
            if (nb) cn[t] = nb[jb + t];
            else {
                const float* r = Xb + (size_t)(jb + t) * ldx;
                cn[t] = r[0] * r[0] + r[1] * r[1] + r[2] * r[2];
            }
        }

        const float* pfB = Xb + (size_t)(jb + row0) * ldx + kkc;

        if constexpr (C >= 16) {
            const float* p = pfB;
            #pragma unroll
            for (int i = 0; i < NC; ++i) { rc[i] = *p; p += cstep; }
        } else {
            #pragma unroll
            for (int i = 0; i < NC; ++i) {
                int e = t + i * 256;
                if (e < CT * KC) { int row = e / KC, kk = e - row * KC;
                    rc[i] = Xb[(size_t)(jb + row) * ldx + kk]; }
            }
        }

        unsigned long long acc2[4][4];
        #pragma unroll
        for (int v = 0; v < 4; ++v)
            #pragma unroll
            for (int u = 0; u < 4; ++u) acc2[v][u] = 0ull;

        #pragma unroll 1                                   // I-cache: keep rolled
        for (int p = 0; p < NPH; ++p) {
            float* csw = (p & 1) ? cs1 : cs0;
            if constexpr (C >= 16) {
                float* st = csw + kkc * CPAD + row0;
                #pragma unroll
                for (int i = 0; i < NC; ++i) st[i * RSTEP] = rc[i];
            } else {
                #pragma unroll
                for (int i = 0; i < NC; ++i) {
                    int e = t + i * 256;
                    if (e < CT * KC) { int row = e / KC, kk = e - row * KC;
                        csw[kk * CPAD + row] = rc[i]; }
                }
            }
            __syncthreads();
            if (p + 1 < NPH) {
                if constexpr (C >= 16) {
                    const float* pn = pfB + (p + 1) * KC;
                    #pragma unroll
                    for (int i = 0; i < NC; ++i) { rc[i] = *pn; pn += cstep; }
                }
            }
            const float* qbase = qsF + (size_t)p * KC * QPAD;
            #pragma unroll
            for (int kk = 0; kk < KC; ++kk) {
                const float* qrow = qbase + kk * QPAD;
                ulonglong2 qa = *(const ulonglong2*)(qrow + ty * 8);
                ulonglong2 qb = *(const ulonglong2*)(qrow + ty * 8 + 4);
                float4 c1 = *(const float4*)(csw + kk * CPAD + tx * 4);
                unsigned long long qd[4] = {qa.x, qa.y, qb.x, qb.y};
                unsigned long long cd[4] = {pack2s(c1.x), pack2s(c1.y),
                                            pack2s(c1.z), pack2s(c1.w)};
                #pragma unroll
                for (int v = 0; v < 4; ++v)
                    #pragma unroll
                    for (int u = 0; u < 4; ++u)
                        ffma2(acc2[v][u], qd[v], cd[u]);
            }
        }
        // distances -> smem tile
        {
            float4 cna = ((const float4*)cn)[tx];
            #pragma unroll
            for (int vp = 0; vp < 4; ++vp) {
                float2 p0 = unpack2(acc2[vp][0]);
                float2 p1 = unpack2(acc2[vp][1]);
                float2 p2 = unpack2(acc2[vp][2]);
                float2 p3 = unpack2(acc2[vp][3]);
                int qA = ty * 8 + 2 * vp;
                float na = qn[qA], nb2 = qn[qA + 1];
                float4 wA, wB;
                wA.x = (na + cna.x) - 2.0f * p0.x;
                wA.y = (na + cna.y) - 2.0f * p1.x;
                wA.z = (na + cna.z) - 2.0f * p2.x;
                wA.w = (na + cna.w) - 2.0f * p3.x;
                wB.x = (nb2 + cna.x) - 2.0f * p0.y;
                wB.y = (nb2 + cna.y) - 2.0f * p1.y;
                wB.z = (nb2 + cna.z) - 2.0f * p2.y;
                wB.w = (nb2 + cna.w) - 2.0f * p3.y;
                *(float4*)(dt + qA * DPAD + tx * 4)       = wA;
                *(float4*)(dt + (qA + 1) * DPAD + tx * 4) = wB;
            }
        }
        __syncthreads();
        // top-k scan
        {
            int q = t >> 2, sub = t & 3;
            const float* drow = dt + q * DPAD;
            float tau = ld[KTOP - 1];
            tau = fminf(tau, __shfl_xor_sync(0xffffffffu, tau, 1));
            tau = fminf(tau, __shfl_xor_sync(0xffffffffu, tau, 2));
            unsigned mask = 0u;
            #pragma unroll
            for (int i = 0; i < 32; ++i) {
                float d = drow[sub + 4 * i];
                mask |= (d < tau) ? (1u << i) : 0u;
            }
            while (mask) {
                int i = __ffs(mask) - 1;
                mask &= mask - 1u;
                int col = sub + 4 * i;
                float d = drow[col];
                if (d < ld[KTOP - 1]) {
                    ld[KTOP - 1] = d; li[KTOP - 1] = jb + col;
                    #pragma unroll
                    for (int s = KTOP - 1; s > 0; --s) {
                        if (ld[s] < ld[s - 1]) {
                            float td = ld[s]; ld[s] = ld[s - 1]; ld[s - 1] = td;
                            int ti = li[s]; li[s] = li[s - 1]; li[s - 1] = ti;
                        }
                    }
                }
            }
        }
        __syncthreads();
    }

    // merge 4 sorted lists per query (smem reuse; launch allocates >= 40960 B)
    float* md = sm;
    int*   mi = (int*)(sm + QT * 4 * KTOP);
    {
        int q = t >> 2, sub = t & 3;
        #pragma unroll
        for (int s = 0; s < KTOP; ++s) {
            md[(q * 4 + sub) * KTOP + s] = ld[s];
            mi[(q * 4 + sub) * KTOP + s] = li[s];
        }
    }
    __syncthreads();
    if (t < QT) {
        int p[4] = {0, 0, 0, 0};
        int* op = out_idx + ((size_t)(b * Nn + q0 + t)) * KTOP;
        for (int kk = 0; kk < KTOP; ++kk) {
            float bd = CUDART_INF_F; int bi = 0x7fffffff; int bs = 0;
            #pragma unroll
            for (int s = 0; s < 4; ++s) {
                if (p[s] < KTOP) {
                    float d = md[(t * 4 + s) * KTOP + p[s]];
                    int  i2 = mi[(t * 4 + s) * KTOP + p[s]];
                    if (d < bd || (d == bd && i2 < bi)) { bd = d; bi = i2; bs = s; }
                }
            }
            #pragma unroll
            for (int s = 0; s < 4; ++s) if (bs == s) p[s]++;
            op[kk] = bi;
        }
    }
}

// ------------------------- gemm8 body (8x4 microtile, dynamic smem) --------
__device__ __forceinline__ void gemm8_body(float* sm,
                                           const float* __restrict__ X, int ldx,
                                           const float* __restrict__ Wt,
                                           const float* __restrict__ bias, int biasFrom,
                                           float* __restrict__ Y, int ldy,
                                           int M, int N2, int K, int gid) {
    constexpr int BM = 128, BN = 64, KC = 16;
    float* Xs = sm;               // [KC][BM+4] stride 132
    float* Ws = sm + KC * 132;    // [KC][BN+4] stride 68
    int t = threadIdx.x;
    int tx = t & 15, ty = t >> 4;
    int mt = M >> 7;
    int m0 = (gid % mt) * BM, n0 = (gid / mt) * BN;
    float acc[8][4];
    #pragma unroll
    for (int v = 0; v < 8; ++v)
        #pragma unroll
        for (int u = 0; u < 4; ++u) acc[v][u] = 0.f;

    #pragma unroll 1
    for (int k0 = 0; k0 < K; k0 += KC) {
        __syncthreads();
        for (int e = t; e < BM * KC; e += 256) {
            int mi_ = e >> 4, kk = e & 15;
            Xs[kk * 132 + mi_] = X[(size_t)(m0 + mi_) * ldx + (k0 + kk)];
        }
        for (int e = t; e < BN * KC; e += 256) {
            int ni = e >> 4, kk = e & 15;
            Ws[kk * 68 + ni] = Wt[(size_t)(n0 + ni) * K + (k0 + kk)];
        }
        __syncthreads();
        #pragma unroll
        for (int kk = 0; kk < KC; ++kk) {
            float4 x1 = *(const float4*)(Xs + kk * 132 + ty * 8);
            float4 x2 = *(const float4*)(Xs + kk * 132 + ty * 8 + 4);
            float4 w  = *(const float4*)(Ws + kk * 68 + tx * 4);
            float xv[8] = {x1.x, x1.y, x1.z, x1.w, x2.x, x2.y, x2.z, x2.w};
            float wv[4] = {w.x, w.y, w.z, w.w};
            #pragma unroll
            for (int v = 0; v < 8; ++v)
                #pragma unroll
                for (int u = 0; u < 4; ++u)
                    acc[v][u] = fmaf(xv[v], wv[u], acc[v][u]);
        }
    }
    #pragma unroll
    for (int v = 0; v < 8; ++v) {
        int m = m0 + ty * 8 + v;
        #pragma unroll
        for (int u = 0; u < 4; ++u) {
            int n = n0 + tx * 4 + u;
            float val = acc[v][u];
            if (n >= biasFrom) val += bias[n - biasFrom];
            Y[(size_t)m * ldy + n] = val;
        }
    }
}

// ------------------------- fused kNN || gemm8 ------------------------------
template<int C>
__global__ __launch_bounds__(256, 2)
void knn_gemm_kernel(const float* __restrict__ X, int ldx,
                     const float* __restrict__ norms, int* __restrict__ out_idx,
                     int knnBlocks,
                     const float* __restrict__ GW, const float* __restrict__ gbias,
                     int biasFrom, float* __restrict__ GY, int gldy,
                     int GM, int GN2, int GK) {
    extern __shared__ float sm[];
    if ((int)blockIdx.x < knnBlocks) {
        knn_body<C>(X, ldx, norms, out_idx, blockIdx.x & 63, blockIdx.x >> 6, sm);
    } else {
        gemm8_body(sm, X, ldx, GW, gbias, biasFrom, GY, gldy, GM, GN2, GK,
                   blockIdx.x - knnBlocks);
    }
}

// ------------------------- fused layer-1 preamble || knn<3> ----------------
static constexpr int KNN_BLKS = 256;
static constexpr int PREP_BLKS = 772;
static constexpr int COPY_BLKS = 64;
static constexpr int GEMM1_BLKS = (Bb * Nn * 128) / 256;   // 8192
__global__ __launch_bounds__(256, 2)
void prep_knn3_kernel(const float* __restrict__ V,
                      const float* __restrict__ g1w, const float* __restrict__ g1b,
                      const float* __restrict__ w1, const float* __restrict__ w2,
                      const float* __restrict__ w3, const float* __restrict__ w4,
                      const float* __restrict__ w5,
                      float* __restrict__ S,
                      float* __restrict__ feat, float* __restrict__ PQ,
                      int* __restrict__ KI) {
    extern __shared__ float sm[];
    if ((int)blockIdx.x < KNN_BLKS) {
        knn_body<3>(V, 3, nullptr, KI, blockIdx.x & 63, blockIdx.x >> 6, sm);
        return;
    }
    int blk = blockIdx.x - KNN_BLKS, t = threadIdx.x;
    if (blk < PREP_BLKS) {
        const int  OC[5] = {128, 256, 256, 128, 64};
        const int  CC[5] = {64, 128, 451, 256, 128};
        const size_t OFF[5] = {OF_WG2, OF_WG3, OF_WS1, OF_WS2, OF_WS3};
        const float* W[5] = {w1, w2, w3, w4, w5};
        const int TOT = 128*64 + 256*128 + 256*451 + 128*256 + 64*128;
        for (int g = blk * 256 + t; g < TOT; g += PREP_BLKS * 256) {
            int rem = g, seg = 0;
            while (rem >= OC[seg] * CC[seg]) { rem -= OC[seg] * CC[seg]; ++seg; }
            int Cc = CC[seg], O = OC[seg];
            int o = rem / Cc, c = rem - o * Cc;
            float a = W[seg][(size_t)o * 2 * Cc + c];
            float b = W[seg][(size_t)o * 2 * Cc + Cc + c];
            float* wc = S + OFF[seg];
            wc[(size_t)o * Cc + c]       = a;
            wc[(size_t)(O + o) * Cc + c] = b - a;
        }
    } else if (blk < PREP_BLKS + COPY_BLKS) {
        int r = (blk - PREP_BLKS) * 256 + t;
        if (r < Bb * Nn) {
            float x = V[(size_t)r * 3 + 0];
            float y = V[(size_t)r * 3 + 1];
            float z = V[(size_t)r * 3 + 2];
            float* fr = feat + (size_t)r * 451;
            fr[0] = x; fr[1] = y; fr[2] = z;
        }
    } else {
        int idx = (blk - PREP_BLKS - COPY_BLKS) * 256 + t;   // r*128 + c
        int r = idx >> 7, c = idx & 127;
        const float* vr = V + (size_t)r * 3;
        float x = vr[0], y = vr[1], z = vr[2];
        int o = c & 63;
        const float* w = g1w + (size_t)o * 6;
        float s;
        if (c < 64) s = x * w[0] + y * w[1] + z * w[2];
        else        s = x * (w[3] - w[0]) + y * (w[4] - w[1]) + z * (w[5] - w[2]) + g1b[o];
        PQ[idx] = s;
    }
}

// ------------------------- small tiled GEMM: Y = X * Wt^T ------------------
__global__ __launch_bounds__(256)
void gemm_kernel(const float* __restrict__ X, int ldx,
                 const float* __restrict__ Wt,
                 const float* __restrict__ bias, int biasFrom,
                 float* __restrict__ Y, int ldy,
                 int M, int N2, int K, int leaky) {
    constexpr int BM = 64, BN = 64, KC = 16;
    __shared__ float Xs[KC][BM + 1];
    __shared__ float Ws[KC][BN + 1];
    int t = threadIdx.x;
    int tx = t & 15, ty = t >> 4;
    int m0 = blockIdx.x * BM, n0 = blockIdx.y * BN;
    float acc[4][4];
    #pragma unroll
    for (int v = 0; v < 4; ++v)
        #pragma unroll
        for (int u = 0; u < 4; ++u) acc[v][u] = 0.f;

    #pragma unroll 1
    for (int k0 = 0; k0 < K; k0 += KC) {
        __syncthreads();
        for (int e = t; e < BM * KC; e += 256) {
            int mi_ = e >> 4, kk = e & 15;
            int m = m0 + mi_, k = k0 + kk;
            Xs[kk][mi_] = (m < M && k < K) ? X[(size_t)m * ldx + k] : 0.f;
        }
        for (int e = t; e < BN * KC; e += 256) {
            int ni = e >> 4, kk = e & 15;
            int n = n0 + ni, k = k0 + kk;
            Ws[kk][ni] = (n < N2 && k < K) ? Wt[(size_t)n * K + k] : 0.f;
        }
        __syncthreads();
        #pragma unroll
        for (int kk = 0; kk < KC; ++kk) {
            float xv[4], wv[4];
            #pragma unroll
            for (int v = 0; v < 4; ++v) xv[v] = Xs[kk][ty + 16 * v];
            #pragma unroll
            for (int u = 0; u < 4; ++u) wv[u] = Ws[kk][tx + 16 * u];
            #pragma unroll
            for (int v = 0; v < 4; ++v)
                #pragma unroll
                for (int u = 0; u < 4; ++u)
                    acc[v][u] = fmaf(xv[v], wv[u], acc[v][u]);
        }
    }
    #pragma unroll
    for (int v = 0; v < 4; ++v) {
        int m = m0 + ty + 16 * v;
        if (m >= M) continue;
        #pragma unroll
        for (int u = 0; u < 4; ++u) {
            int n = n0 + tx + 16 * u;
            if (n >= N2) continue;
            float val = acc[v][u];
            if (n >= biasFrom) val += bias[n - biasFrom];
            if (leaky) val = LRELU(val);
            Y[(size_t)m * ldy + n] = val;
        }
    }
}

// ------------------------- gather + max + leaky (+ optional row norm) ------
__global__ void gathermax_kernel(const float* __restrict__ PQ, int O,
                                 const int* __restrict__ idx, int k, int nPer,
                                 float* __restrict__ out, int ldo,
                                 float* __restrict__ nrmOut) {
    int row = blockIdx.x;
    int b = row / nPer;
    __shared__ int sidx[32];
    __shared__ float wpart[8];
    if (threadIdx.x < k) sidx[threadIdx.x] = idx[(size_t)row * k + threadIdx.x];
    __syncthreads();
    int ld2 = 2 * O;
    const float* Pb = PQ + (size_t)b * nPer * ld2;
    const float* Qr = PQ + (size_t)row * ld2 + O;
    float* orow = out + (size_t)row * ldo;
    float sq = 0.f;
    for (int o = threadIdx.x; o < O; o += blockDim.x) {
        float m = -CUDART_INF_F;
        for (int kk = 0; kk < k; ++kk)
            m = fmaxf(m, Pb[(size_t)sidx[kk] * ld2 + o]);
        float v = m + Qr[o];
        v = LRELU(v);
        orow[o] = v;
        sq = fmaf(v, v, sq);
    }
    if (nrmOut) {
        #pragma unroll
        for (int off = 16; off; off >>= 1) sq += __shfl_xor_sync(0xffffffffu, sq, off);
        int lane = threadIdx.x & 31, w = threadIdx.x >> 5;
        int nw = blockDim.x >> 5;
        if (!lane) wpart[w] = sq;
        __syncthreads();
        if (threadIdx.x == 0) {
            float s = 0.f;
            for (int i = 0; i < nw; ++i) s += wpart[i];
            nrmOut[row] = s;
        }
    }
}

// ------------------------- weighted pooling onto joints --------------------
__global__ __launch_bounds__(256)
void pool_kernel(const float* __restrict__ W, const float* __restrict__ feat,
                 float* __restrict__ pooled) {
    __shared__ float Ws_[24][64];
    __shared__ float swj[24];
    int t = threadIdx.x;
    int b = blockIdx.y;
    int cl = t & 63, jg = t >> 6;           // 4 groups x 6 joints
    int c = blockIdx.x * 64 + cl;
    float acc[6] = {0, 0, 0, 0, 0, 0};
    float wsum[6] = {0, 0, 0, 0, 0, 0};
    const float* Wb = W + (size_t)b * Jj * Nn;
    const float* fb = feat + (size_t)b * Nn * 451;
    for (int n0 = 0; n0 < Nn; n0 += 64) {
        __syncthreads();
        for (int e = t; e < 24 * 64; e += 256) {
            int j = e >> 6, nn = e & 63;
            Ws_[j][nn] = Wb[(size_t)j * Nn + n0 + nn];
        }
        __syncthreads();
        for (int nn = 0; nn < 64; ++nn) {
            float f = (c < 451) ? fb[(size_t)(n0 + nn) * 451 + c] : 0.f;
            #pragma unroll
            for (int jj = 0; jj < 6; ++jj) {
                float wv = Ws_[jg * 6 + jj][nn];
                acc[jj] = fmaf(wv, f, acc[jj]);
                if (cl == 0) wsum[jj] += wv;
            }
        }
    }
    __syncthreads();
    if (cl == 0)
        #pragma unroll
        for (int jj = 0; jj < 6; ++jj) swj[jg * 6 + jj] = wsum[jj];
    __syncthreads();
    if (c < 451)
        #pragma unroll
        for (int jj = 0; jj < 6; ++jj) {
            int j = jg * 6 + jj;
            pooled[((size_t)b * Jj + j) * 451 + c] = acc[jj] / (swj[j] + 1e-5f);
        }
}

// ---------------------------------------------------------------------------
extern "C" void kernel_launch(void* const* d_in, const int* in_sizes, int n_in,
                              void* d_out, int out_size) {
    const float* V   = (const float*)d_in[0];
    const float* Wmt = (const float*)d_in[1];
    const int*   sIx = (const int*)d_in[2];
    const float* g1w = (const float*)d_in[3];  const float* g1b = (const float*)d_in[4];
    const float* g2w = (const float*)d_in[5];  const float* g2b = (const float*)d_in[6];
    const float* g3w = (const float*)d_in[7];  const float* g3b = (const float*)d_in[8];
    const float* s1w = (const float*)d_in[9];  const float* s1b = (const float*)d_in[10];
    const float* s2w = (const float*)d_in[11]; const float* s2b = (const float*)d_in[12];
    const float* s3w = (const float*)d_in[13]; const float* s3b = (const float*)d_in[14];
    const float* m1w = (const float*)d_in[15]; const float* m1b = (const float*)d_in[16];
    const float* m2w = (const float*)d_in[17]; const float* m2b = (const float*)d_in[18];
    const float* m3w = (const float*)d_in[19]; const float* m3b = (const float*)d_in[20];
    float* out = (float*)d_out;

    float* S = nullptr; cudaGetSymbolAddress((void**)&S, d_SF);
    int*  KI = nullptr; cudaGetSymbolAddress((void**)&KI, d_SI);

    float* feat   = S + OF_FEAT;
    float* PQ     = S + OF_PQ;
    float* nrm    = S + OF_NORM;
    float* pooled = S + OF_POOL;
    float* joints = S + OF_JNT;
    float* t1     = S + OF_T1;
    float* t2     = S + OF_T2;
    float* wg2 = S + OF_WG2; float* wg3 = S + OF_WG3;
    float* ws1 = S + OF_WS1; float* ws2 = S + OF_WS2; float* ws3 = S + OF_WS3;

    // dynamic smem: knn base(C) = C*68 + 2*16*132 + 64*132 + 192 floats;
    // gemm8 needs 16*(132+68)*4 = 12800 B; merge needs 40960 B.
    const int SM_MERGE = 64 * 4 * KTOP * 2 * 4;                         // 40960
    const int SM_C3   = (3 * 68 + 2 * 3 * 132 + 64 * 132 + 192) * 4;    // 38544
    const int SM_C64  = (64 * 68 + 2 * 16 * 132 + 64 * 132 + 192) * 4;  // 68864
    const int SM_C128 = (128 * 68 + 2 * 16 * 132 + 64 * 132 + 192) * 4; // 86272
    const int SM_K3   = (SM_C3 > SM_MERGE) ? SM_C3 : SM_MERGE;          // 40960
    cudaFuncSetAttribute((const void*)prep_knn3_kernel,
                         cudaFuncAttributeMaxDynamicSharedMemorySize, SM_K3);
    cudaFuncSetAttribute((const void*)knn_gemm_kernel<64>,
                         cudaFuncAttributeMaxDynamicSharedMemorySize, SM_C64);
    cudaFuncSetAttribute((const void*)knn_gemm_kernel<128>,
                         cudaFuncAttributeMaxDynamicSharedMemorySize, SM_C128);

    const int M = Bb * Nn;               // 16384

    // ---- layer 1: fused (prep + copyV + K=3 PQ gemm) || knn<3>
    prep_knn3_kernel<<<KNN_BLKS + PREP_BLKS + COPY_BLKS + GEMM1_BLKS, 256, SM_K3>>>(
        V, g1w, g1b, g2w, g3w, s1w, s2w, s3w, S, feat, PQ, KI);            // 1
    gathermax_kernel<<<M, 64>>>(PQ, 64, KI, KTOP, Nn, feat + 3, 451, nrm); // 2

    // ---- layer 2: fused knn<64> || gemm2 (both consume feat+3)
    knn_gemm_kernel<64><<<KNN_BLKS + 512, 256, SM_C64>>>(
        feat + 3, 451, nrm, KI, KNN_BLKS,
        wg2, g2b, 128, PQ, 256, M, 256, 64);                               // 3
    gathermax_kernel<<<M, 128>>>(PQ, 128, KI, KTOP, Nn, feat + 67, 451, nrm); // 4 (ncu)

    // ---- layer 3: fused knn<128> || gemm3 (both consume feat+67)
    knn_gemm_kernel<128><<<KNN_BLKS + 1024, 256, SM_C128>>>(
        feat + 67, 451, nrm, KI, KNN_BLKS,
        wg3, g3b, 256, PQ, 512, M, 512, 128);                              // 5
    gathermax_kernel<<<M, 256>>>(PQ, 256, KI, KTOP, Nn, feat + 195, 451, nullptr);

    // ---- weighted pooling onto 24 joints
    pool_kernel<<<dim3(8, Bb), 256>>>(Wmt, feat, pooled);

    const int MJ = Bb * Jj;              // 96
    // ---- skeleton edge conv 1 (C=451 -> O=256)
    gemm_kernel<<<dim3(2, 8), 256>>>(pooled, 451, ws1, s1b, 256, PQ, 512, MJ, 512, 451, 0);
    gathermax_kernel<<<MJ, 256>>>(PQ, 256, sIx, 4, Jj, joints, 448, nullptr);
    // ---- skeleton edge conv 2 (C=256 -> O=128)
    gemm_kernel<<<dim3(2, 4), 256>>>(joints, 448, ws2, s2b, 128, PQ, 256, MJ, 256, 256, 0);
    gathermax_kernel<<<MJ, 128>>>(PQ, 128, sIx, 4, Jj, joints + 256, 448, nullptr);
    // ---- skeleton edge conv 3 (C=128 -> O=64)
    gemm_kernel<<<dim3(2, 2), 256>>>(joints + 256, 448, ws3, s3b, 64, PQ, 128, MJ, 128, 128, 0);
    gathermax_kernel<<<MJ, 64>>>(PQ, 64, sIx, 4, Jj, joints + 384, 448, nullptr);

    // ---- joint MLP 448 -> 512 -> 256 -> 3
    gemm_kernel<<<dim3(2, 8), 256>>>(joints, 448, m1w, m1b, 0, t1, 512, MJ, 512, 448, 1);
    gemm_kernel<<<dim3(2, 4), 256>>>(t1, 512, m2w, m2b, 0, t2, 256, MJ, 256, 512, 1);
    gemm_kernel<<<dim3(2, 1), 256>>>(t2, 256, m3w, m3b, 0, out, 3, MJ, 3, 256, 0);
}

// round 16
// speedup vs baseline: 1.0992x; 1.0992x over previous
#include <cuda_runtime.h>
#include <cstdint>
#include <cstddef>
#include <math_constants.h>

// ---------------------------------------------------------------------------
// JointNet: DGCNN geo-net (3 dynamic-kNN edge convs) + weighted joint pooling
//           + skeleton edge convs (fixed one-ring) + joint MLP.
// Edge conv rewrite:  max_k leaky(w1*(xj-xi)+w2*xi+b)
//                   = leaky( Q[i] + max_k P[idx[i,k]] ),
//                     P = X*w1^T, Q = X*(w2-w1)^T + b
// R16: exact R14 revert (R15's rolled phase loop regressed) + float4
//      gathermax (LDG.128 gathers amortize addressing 4x; width-O/4
//      shuffle norm reduction; G=512/O rows per 128-thread block).
// ---------------------------------------------------------------------------

static constexpr int Bb = 4, Nn = 4096, Jj = 24, KTOP = 20;

#define LRELU(x) ((x) >= 0.f ? (x) : 0.2f * (x))

// ------------------------- scratch (floats) --------------------------------
static constexpr size_t OF_FEAT = 0;                       // [4][4096][451]
static constexpr size_t SZ_FEAT = (size_t)Bb * Nn * 451;
static constexpr size_t OF_PQ   = OF_FEAT + SZ_FEAT;       // [4*4096][512] max
static constexpr size_t SZ_PQ   = (size_t)Bb * Nn * 512;
static constexpr size_t OF_NORM = OF_PQ + SZ_PQ;           // [4*4096]
static constexpr size_t SZ_NORM = (size_t)Bb * Nn;
static constexpr size_t OF_POOL = OF_NORM + SZ_NORM;       // [96][451]
static constexpr size_t SZ_POOL = (size_t)Bb * Jj * 451;
static constexpr size_t OF_JNT  = OF_POOL + SZ_POOL;       // [96][448]
static constexpr size_t SZ_JNT  = (size_t)Bb * Jj * 448;
static constexpr size_t OF_T1   = OF_JNT + SZ_JNT;         // [96][512]
static constexpr size_t SZ_T1   = (size_t)Bb * Jj * 512;
static constexpr size_t OF_T2   = OF_T1 + SZ_T1;           // [96][256]
static constexpr size_t SZ_T2   = (size_t)Bb * Jj * 256;
static constexpr size_t OF_WG1  = OF_T2 + SZ_T2;   static constexpr size_t SZ_WG1 = 2 * 64 * 3;
static constexpr size_t OF_WG2  = OF_WG1 + SZ_WG1; static constexpr size_t SZ_WG2 = 2 * 128 * 64;
static constexpr size_t OF_WG3  = OF_WG2 + SZ_WG2; static constexpr size_t SZ_WG3 = 2 * 256 * 128;
static constexpr size_t OF_WS1  = OF_WG3 + SZ_WG3; static constexpr size_t SZ_WS1 = 2 * 256 * 451;
static constexpr size_t OF_WS2  = OF_WS1 + SZ_WS1; static constexpr size_t SZ_WS2 = 2 * 128 * 256;
static constexpr size_t OF_WS3  = OF_WS2 + SZ_WS2; static constexpr size_t SZ_WS3 = 2 * 64 * 128;
static constexpr size_t SF_TOTAL = OF_WS3 + SZ_WS3;

__device__ float d_SF[SF_TOTAL];
__device__ int   d_SI[(size_t)Bb * Nn * KTOP];

// ------------------------- f32x2 helpers (sm_10x packed fp32) --------------
__device__ __forceinline__ unsigned long long pack2s(float v) {
    unsigned long long r;
    asm("mov.b64 %0, {%1, %2};" : "=l"(r) : "f"(v), "f"(v));
    return r;
}
__device__ __forceinline__ float2 unpack2(unsigned long long v) {
    float2 r;
    asm("mov.b64 {%0, %1}, %2;" : "=f"(r.x), "=f"(r.y) : "l"(v));
    return r;
}
__device__ __forceinline__ void ffma2(unsigned long long& d,
                                      unsigned long long a, unsigned long long b) {
    asm("fma.rn.f32x2 %0, %1, %2, %0;" : "+l"(d) : "l"(a), "l"(b));
}

// ------------------------- kNN body (exact top-20) -------------------------
// 64 queries x 128-cand tiles; resident query slab; double-buffered KC=16
// candidate staging (strength-reduced addressing); query-paired f32x2
// microtile; shared-tau masks; 4 threads/query sorted top-20 + 4-way merge.
// If norms==nullptr (C==3), row norms are computed directly from X.
template<int C>
__device__ __forceinline__ void knn_body(const float* __restrict__ X, int ldx,
                                         const float* __restrict__ norms,
                                         int* __restrict__ out_idx,
                                         int bx, int b, float* sm) {
    constexpr int KC = (C < 16) ? C : 16;
    constexpr int NPH = C / KC;
    constexpr int QT = 64, CT = 128;
    constexpr int CPAD = 132, QPAD = 68, DPAD = 132;
    constexpr int NC = (CT * KC + 255) / 256;
    constexpr int RSTEP = 256 / KC;

    float* qsF = sm;                      // [C][QPAD]  resident
    float* cs0 = qsF + C * QPAD;          // [KC][CPAD] buffer 0
    float* cs1 = cs0 + KC * CPAD;         // [KC][CPAD] buffer 1
    float* dt  = cs1 + KC * CPAD;         // [QT][DPAD]
    float* cn  = dt + QT * DPAD;          // [CT]
    float* qn  = cn + CT;                 // [QT]

    const int t  = threadIdx.x;
    const int tx = t & 31, ty = t >> 5;
    const int q0 = bx * QT;
    const float* Xb = X + (size_t)b * Nn * ldx;
    const float* nb = norms ? norms + (size_t)b * Nn : nullptr;

    if (t < QT) {
        if (nb) qn[t] = nb[q0 + t];
        else {
            const float* r = Xb + (size_t)(q0 + t) * ldx;
            qn[t] = r[0] * r[0] + r[1] * r[1] + r[2] * r[2];
        }
    }
    // resident query slab
    if constexpr (C >= 16) {
        constexpr int QIT = QT * C / 256;
        constexpr int QSTEP = 256 / C;
        const int qcol = t & (C - 1);
        const int qrow0 = t / C;
        float* qdst = qsF + qcol * QPAD + qrow0;
        const float* qsrc = Xb + (size_t)(q0 + qrow0) * ldx + qcol;
        const size_t qinc = (size_t)QSTEP * ldx;
        #pragma unroll 4
        for (int j = 0; j < QIT; ++j) { qdst[j * QSTEP] = *qsrc; qsrc += qinc; }
    } else {
        for (int e = t; e < QT * C; e += 256) {
            int row = e / C, col = e - row * C;
            qsF[col * QPAD + row] = Xb[(size_t)(q0 + row) * ldx + col];
        }
    }

    float ld[KTOP]; int li[KTOP];
    #pragma unroll
    for (int s = 0; s < KTOP; ++s) { ld[s] = CUDART_INF_F; li[s] = 0x7fffffff; }

    float rc[NC];
    const int kkc  = t & (KC - 1);
    const int row0 = t / KC;
    const size_t cstep = (size_t)RSTEP * ldx;

    for (int jb = 0; jb < Nn; jb += CT) {
        if (t < CT) {
            if (nb) cn[t] = nb[jb + t];
            else {
                const float* r = Xb + (size_t)(jb + t) * ldx;
                cn[t] = r[0] * r[0] + r[1] * r[1] + r[2] * r[2];
            }
        }

        const float* pfB = Xb + (size_t)(jb + row0) * ldx + kkc;

        if constexpr (C >= 16) {
            const float* p = pfB;
            #pragma unroll
            for (int i = 0; i < NC; ++i) { rc[i] = *p; p += cstep; }
        } else {
            #pragma unroll
            for (int i = 0; i < NC; ++i) {
                int e = t + i * 256;
                if (e < CT * KC) { int row = e / KC, kk = e - row * KC;
                    rc[i] = Xb[(size_t)(jb + row) * ldx + kk]; }
            }
        }

        unsigned long long acc2[4][4];
        #pragma unroll
        for (int v = 0; v < 4; ++v)
            #pragma unroll
            for (int u = 0; u < 4; ++u) acc2[v][u] = 0ull;

        #pragma unroll
        for (int p = 0; p < NPH; ++p) {
            float* csw = (p & 1) ? cs1 : cs0;
            if constexpr (C >= 16) {
                float* st = csw + kkc * CPAD + row0;
                #pragma unroll
                for (int i = 0; i < NC; ++i) st[i * RSTEP] = rc[i];
            } else {
                #pragma unroll
                for (int i = 0; i < NC; ++i) {
                    int e = t + i * 256;
                    if (e < CT * KC) { int row = e / KC, kk = e - row * KC;
                        csw[kk * CPAD + row] = rc[i]; }
                }
            }
            __syncthreads();
            if (p + 1 < NPH) {
                if constexpr (C >= 16) {
                    const float* pn = pfB + (p + 1) * KC;
                    #pragma unroll
                    for (int i = 0; i < NC; ++i) { rc[i] = *pn; pn += cstep; }
                }
            }
            #pragma unroll
            for (int kk = 0; kk < KC; ++kk) {
                const float* qrow = qsF + (p * KC + kk) * QPAD;
                ulonglong2 qa = *(const ulonglong2*)(qrow + ty * 8);
                ulonglong2 qb = *(const ulonglong2*)(qrow + ty * 8 + 4);
                float4 c1 = *(const float4*)(csw + kk * CPAD + tx * 4);
                unsigned long long qd[4] = {qa.x, qa.y, qb.x, qb.y};
                unsigned long long cd[4] = {pack2s(c1.x), pack2s(c1.y),
                                            pack2s(c1.z), pack2s(c1.w)};
                #pragma unroll
                for (int v = 0; v < 4; ++v)
                    #pragma unroll
                    for (int u = 0; u < 4; ++u)
                        ffma2(acc2[v][u], qd[v], cd[u]);
            }
        }
        // distances -> smem tile
        {
            float4 cna = ((const float4*)cn)[tx];
            #pragma unroll
            for (int vp = 0; vp < 4; ++vp) {
                float2 p0 = unpack2(acc2[vp][0]);
                float2 p1 = unpack2(acc2[vp][1]);
                float2 p2 = unpack2(acc2[vp][2]);
                float2 p3 = unpack2(acc2[vp][3]);
                int qA = ty * 8 + 2 * vp;
                float na = qn[qA], nb2 = qn[qA + 1];
                float4 wA, wB;
                wA.x = (na + cna.x) - 2.0f * p0.x;
                wA.y = (na + cna.y) - 2.0f * p1.x;
                wA.z = (na + cna.z) - 2.0f * p2.x;
                wA.w = (na + cna.w) - 2.0f * p3.x;
                wB.x = (nb2 + cna.x) - 2.0f * p0.y;
                wB.y = (nb2 + cna.y) - 2.0f * p1.y;
                wB.z = (nb2 + cna.z) - 2.0f * p2.y;
                wB.w = (nb2 + cna.w) - 2.0f * p3.y;
                *(float4*)(dt + qA * DPAD + tx * 4)       = wA;
                *(float4*)(dt + (qA + 1) * DPAD + tx * 4) = wB;
            }
        }
        __syncthreads();
        // top-k scan
        {
            int q = t >> 2, sub = t & 3;
            const float* drow = dt + q * DPAD;
            float tau = ld[KTOP - 1];
            tau = fminf(tau, __shfl_xor_sync(0xffffffffu, tau, 1));
            tau = fminf(tau, __shfl_xor_sync(0xffffffffu, tau, 2));
            unsigned mask = 0u;
            #pragma unroll
            for (int i = 0; i < 32; ++i) {
                float d = drow[sub + 4 * i];
                mask |= (d < tau) ? (1u << i) : 0u;
            }
            while (mask) {
                int i = __ffs(mask) - 1;
                mask &= mask - 1u;
                int col = sub + 4 * i;
                float d = drow[col];
                if (d < ld[KTOP - 1]) {
                    ld[KTOP - 1] = d; li[KTOP - 1] = jb + col;
                    #pragma unroll
                    for (int s = KTOP - 1; s > 0; --s) {
                        if (ld[s] < ld[s - 1]) {
                            float td = ld[s]; ld[s] = ld[s - 1]; ld[s - 1] = td;
                            int ti = li[s]; li[s] = li[s - 1]; li[s - 1] = ti;
                        }
                    }
                }
            }
        }
        __syncthreads();
    }

    // merge 4 sorted lists per query (smem reuse; launch allocates >= 40960 B)
    float* md = sm;
    int*   mi = (int*)(sm + QT * 4 * KTOP);
    {
        int q = t >> 2, sub = t & 3;
        #pragma unroll
        for (int s = 0; s < KTOP; ++s) {
            md[(q * 4 + sub) * KTOP + s] = ld[s];
            mi[(q * 4 + sub) * KTOP + s] = li[s];
        }
    }
    __syncthreads();
    if (t < QT) {
        int p[4] = {0, 0, 0, 0};
        int* op = out_idx + ((size_t)(b * Nn + q0 + t)) * KTOP;
        for (int kk = 0; kk < KTOP; ++kk) {
            float bd = CUDART_INF_F; int bi = 0x7fffffff; int bs = 0;
            #pragma unroll
            for (int s = 0; s < 4; ++s) {
                if (p[s] < KTOP) {
                    float d = md[(t * 4 + s) * KTOP + p[s]];
                    int  i2 = mi[(t * 4 + s) * KTOP + p[s]];
                    if (d < bd || (d == bd && i2 < bi)) { bd = d; bi = i2; bs = s; }
                }
            }
            #pragma unroll
            for (int s = 0; s < 4; ++s) if (bs == s) p[s]++;
            op[kk] = bi;
        }
    }
}

// ------------------------- gemm8 body (8x4 microtile, dynamic smem) --------
__device__ __forceinline__ void gemm8_body(float* sm,
                                           const float* __restrict__ X, int ldx,
                                           const float* __restrict__ Wt,
                                           const float* __restrict__ bias, int biasFrom,
                                           float* __restrict__ Y, int ldy,
                                           int M, int N2, int K, int gid) {
    constexpr int BM = 128, BN = 64, KC = 16;
    float* Xs = sm;               // [KC][BM+4] stride 132
    float* Ws = sm + KC * 132;    // [KC][BN+4] stride 68
    int t = threadIdx.x;
    int tx = t & 15, ty = t >> 4;
    int mt = M >> 7;
    int m0 = (gid % mt) * BM, n0 = (gid / mt) * BN;
    float acc[8][4];
    #pragma unroll
    for (int v = 0; v < 8; ++v)
        #pragma unroll
        for (int u = 0; u < 4; ++u) acc[v][u] = 0.f;

    for (int k0 = 0; k0 < K; k0 += KC) {
        __syncthreads();
        for (int e = t; e < BM * KC; e += 256) {
            int mi_ = e >> 4, kk = e & 15;
            Xs[kk * 132 + mi_] = X[(size_t)(m0 + mi_) * ldx + (k0 + kk)];
        }
        for (int e = t; e < BN * KC; e += 256) {
            int ni = e >> 4, kk = e & 15;
            Ws[kk * 68 + ni] = Wt[(size_t)(n0 + ni) * K + (k0 + kk)];
        }
        __syncthreads();
        #pragma unroll
        for (int kk = 0; kk < KC; ++kk) {
            float4 x1 = *(const float4*)(Xs + kk * 132 + ty * 8);
            float4 x2 = *(const float4*)(Xs + kk * 132 + ty * 8 + 4);
            float4 w  = *(const float4*)(Ws + kk * 68 + tx * 4);
            float xv[8] = {x1.x, x1.y, x1.z, x1.w, x2.x, x2.y, x2.z, x2.w};
            float wv[4] = {w.x, w.y, w.z, w.w};
            #pragma unroll
            for (int v = 0; v < 8; ++v)
                #pragma unroll
                for (int u = 0; u < 4; ++u)
                    acc[v][u] = fmaf(xv[v], wv[u], acc[v][u]);
        }
    }
    #pragma unroll
    for (int v = 0; v < 8; ++v) {
        int m = m0 + ty * 8 + v;
        #pragma unroll
        for (int u = 0; u < 4; ++u) {
            int n = n0 + tx * 4 + u;
            float val = acc[v][u];
            if (n >= biasFrom) val += bias[n - biasFrom];
            Y[(size_t)m * ldy + n] = val;
        }
    }
}

// ------------------------- fused kNN || gemm8 ------------------------------
template<int C>
__global__ __launch_bounds__(256, 2)
void knn_gemm_kernel(const float* __restrict__ X, int ldx,
                     const float* __restrict__ norms, int* __restrict__ out_idx,
                     int knnBlocks,
                     const float* __restrict__ GW, const float* __restrict__ gbias,
                     int biasFrom, float* __restrict__ GY, int gldy,
                     int GM, int GN2, int GK) {
    extern __shared__ float sm[];
    if ((int)blockIdx.x < knnBlocks) {
        knn_body<C>(X, ldx, norms, out_idx, blockIdx.x & 63, blockIdx.x >> 6, sm);
    } else {
        gemm8_body(sm, X, ldx, GW, gbias, biasFrom, GY, gldy, GM, GN2, GK,
                   blockIdx.x - knnBlocks);
    }
}

// ------------------------- fused layer-1 preamble || knn<3> ----------------
static constexpr int KNN_BLKS = 256;
static constexpr int PREP_BLKS = 772;
static constexpr int COPY_BLKS = 64;
static constexpr int GEMM1_BLKS = (Bb * Nn * 128) / 256;   // 8192
__global__ __launch_bounds__(256, 2)
void prep_knn3_kernel(const float* __restrict__ V,
                      const float* __restrict__ g1w, const float* __restrict__ g1b,
                      const float* __restrict__ w1, const float* __restrict__ w2,
                      const float* __restrict__ w3, const float* __restrict__ w4,
                      const float* __restrict__ w5,
                      float* __restrict__ S,
                      float* __restrict__ feat, float* __restrict__ PQ,
                      int* __restrict__ KI) {
    extern __shared__ float sm[];
    if ((int)blockIdx.x < KNN_BLKS) {
        knn_body<3>(V, 3, nullptr, KI, blockIdx.x & 63, blockIdx.x >> 6, sm);
        return;
    }
    int blk = blockIdx.x - KNN_BLKS, t = threadIdx.x;
    if (blk < PREP_BLKS) {
        const int  OC[5] = {128, 256, 256, 128, 64};
        const int  CC[5] = {64, 128, 451, 256, 128};
        const size_t OFF[5] = {OF_WG2, OF_WG3, OF_WS1, OF_WS2, OF_WS3};
        const float* W[5] = {w1, w2, w3, w4, w5};
        const int TOT = 128*64 + 256*128 + 256*451 + 128*256 + 64*128;
        for (int g = blk * 256 + t; g < TOT; g += PREP_BLKS * 256) {
            int rem = g, seg = 0;
            while (rem >= OC[seg] * CC[seg]) { rem -= OC[seg] * CC[seg]; ++seg; }
            int Cc = CC[seg], O = OC[seg];
            int o = rem / Cc, c = rem - o * Cc;
            float a = W[seg][(size_t)o * 2 * Cc + c];
            float b = W[seg][(size_t)o * 2 * Cc + Cc + c];
            float* wc = S + OFF[seg];
            wc[(size_t)o * Cc + c]       = a;
            wc[(size_t)(O + o) * Cc + c] = b - a;
        }
    } else if (blk < PREP_BLKS + COPY_BLKS) {
        int r = (blk - PREP_BLKS) * 256 + t;
        if (r < Bb * Nn) {
            float x = V[(size_t)r * 3 + 0];
            float y = V[(size_t)r * 3 + 1];
            float z = V[(size_t)r * 3 + 2];
            float* fr = feat + (size_t)r * 451;
            fr[0] = x; fr[1] = y; fr[2] = z;
        }
    } else {
        int idx = (blk - PREP_BLKS - COPY_BLKS) * 256 + t;   // r*128 + c
        int r = idx >> 7, c = idx & 127;
        const float* vr = V + (size_t)r * 3;
        float x = vr[0], y = vr[1], z = vr[2];
        int o = c & 63;
        const float* w = g1w + (size_t)o * 6;
        float s;
        if (c < 64) s = x * w[0] + y * w[1] + z * w[2];
        else        s = x * (w[3] - w[0]) + y * (w[4] - w[1]) + z * (w[5] - w[2]) + g1b[o];
        PQ[idx] = s;
    }
}

// ------------------------- small tiled GEMM: Y = X * Wt^T ------------------
__global__ __launch_bounds__(256)
void gemm_kernel(const float* __restrict__ X, int ldx,
                 const float* __restrict__ Wt,
                 const float* __restrict__ bias, int biasFrom,
                 float* __restrict__ Y, int ldy,
                 int M, int N2, int K, int leaky) {
    constexpr int BM = 64, BN = 64, KC = 16;
    __shared__ float Xs[KC][BM + 1];
    __shared__ float Ws[KC][BN + 1];
    int t = threadIdx.x;
    int tx = t & 15, ty = t >> 4;
    int m0 = blockIdx.x * BM, n0 = blockIdx.y * BN;
    float acc[4][4];
    #pragma unroll
    for (int v = 0; v < 4; ++v)
        #pragma unroll
        for (int u = 0; u < 4; ++u) acc[v][u] = 0.f;

    for (int k0 = 0; k0 < K; k0 += KC) {
        __syncthreads();
        for (int e = t; e < BM * KC; e += 256) {
            int mi_ = e >> 4, kk = e & 15;
            int m = m0 + mi_, k = k0 + kk;
            Xs[kk][mi_] = (m < M && k < K) ? X[(size_t)m * ldx + k] : 0.f;
        }
        for (int e = t; e < BN * KC; e += 256) {
            int ni = e >> 4, kk = e & 15;
            int n = n0 + ni, k = k0 + kk;
            Ws[kk][ni] = (n < N2 && k < K) ? Wt[(size_t)n * K + k] : 0.f;
        }
        __syncthreads();
        #pragma unroll
        for (int kk = 0; kk < KC; ++kk) {
            float xv[4], wv[4];
            #pragma unroll
            for (int v = 0; v < 4; ++v) xv[v] = Xs[kk][ty + 16 * v];
            #pragma unroll
            for (int u = 0; u < 4; ++u) wv[u] = Ws[kk][tx + 16 * u];
            #pragma unroll
            for (int v = 0; v < 4; ++v)
                #pragma unroll
                for (int u = 0; u < 4; ++u)
                    acc[v][u] = fmaf(xv[v], wv[u], acc[v][u]);
        }
    }
    #pragma unroll
    for (int v = 0; v < 4; ++v) {
        int m = m0 + ty + 16 * v;
        if (m >= M) continue;
        #pragma unroll
        for (int u = 0; u < 4; ++u) {
            int n = n0 + tx + 16 * u;
            if (n >= N2) continue;
            float val = acc[v][u];
            if (n >= biasFrom) val += bias[n - biasFrom];
            if (leaky) val = LRELU(val);
            Y[(size_t)m * ldy + n] = val;
        }
    }
}

// ------------------------- gather + max + leaky, float4 gathers ------------
// Block = 128 threads, G = 512/O rows per block; thread handles 4 channels.
// out[row][4o..4o+3] = leaky( Q[row][...] + max_k P[idx[row][k]][...] ).
// If nrmOut != null (requires O/4 <= 32), also writes sum_o out^2.
__global__ __launch_bounds__(128)
void gathermax4_kernel(const float* __restrict__ PQ, int O,
                       const int* __restrict__ idx, int k, int nPer,
                       float* __restrict__ out, int ldo,
                       float* __restrict__ nrmOut) {
    __shared__ int sidx[8 * 32];               // up to G=8 rows x k<=32
    const int O4 = O >> 2;
    const int G  = 512 / O;
    const int t  = threadIdx.x;
    const int g  = t / O4, o4 = t - g * O4;
    const int row = blockIdx.x * G + g;

    for (int e = t; e < G * k; e += 128) {
        int r2 = blockIdx.x * G + e / k;
        sidx[e] = idx[(size_t)r2 * k + (e % k)];
    }
    __syncthreads();

    const int b = row / nPer;
    const int ld2 = 2 * O;
    const float* Pb = PQ + (size_t)b * nPer * ld2;
    const float* Qr = PQ + (size_t)row * ld2 + O;
    const int* myidx = sidx + g * k;

    float4 m = make_float4(-CUDART_INF_F, -CUDART_INF_F, -CUDART_INF_F, -CUDART_INF_F);
    for (int kk = 0; kk < k; ++kk) {
        const float4 v = *(const float4*)(Pb + (size_t)myidx[kk] * ld2 + 4 * o4);
        m.x = fmaxf(m.x, v.x); m.y = fmaxf(m.y, v.y);
        m.z = fmaxf(m.z, v.z); m.w = fmaxf(m.w, v.w);
    }
    const float4 q = *(const float4*)(Qr + 4 * o4);
    float r0 = LRELU(m.x + q.x);
    float r1 = LRELU(m.y + q.y);
    float r2 = LRELU(m.z + q.z);
    float r3 = LRELU(m.w + q.w);
    float* orow = out + (size_t)row * ldo + 4 * o4;
    orow[0] = r0; orow[1] = r1; orow[2] = r2; orow[3] = r3;

    if (nrmOut) {                              // O4 is 16 or 32 here
        float sq = r0 * r0 + r1 * r1 + r2 * r2 + r3 * r3;
        for (int off = O4 >> 1; off; off >>= 1)
            sq += __shfl_xor_sync(0xffffffffu, sq, off, 32);
        if (o4 == 0) nrmOut[row] = sq;
    }
}

// ------------------------- weighted pooling onto joints --------------------
__global__ __launch_bounds__(256)
void pool_kernel(const float* __restrict__ W, const float* __restrict__ feat,
                 float* __restrict__ pooled) {
    __shared__ float Ws_[24][64];
    __shared__ float swj[24];
    int t = threadIdx.x;
    int b = blockIdx.y;
    int cl = t & 63, jg = t >> 6;           // 4 groups x 6 joints
    int c = blockIdx.x * 64 + cl;
    float acc[6] = {0, 0, 0, 0, 0, 0};
    float wsum[6] = {0, 0, 0, 0, 0, 0};
    const float* Wb = W + (size_t)b * Jj * Nn;
    const float* fb = feat + (size_t)b * Nn * 451;
    for (int n0 = 0; n0 < Nn; n0 += 64) {
        __syncthreads();
        for (int e = t; e < 24 * 64; e += 256) {
            int j = e >> 6, nn = e & 63;
            Ws_[j][nn] = Wb[(size_t)j * Nn + n0 + nn];
        }
        __syncthreads();
        for (int nn = 0; nn < 64; ++nn) {
            float f = (c < 451) ? fb[(size_t)(n0 + nn) * 451 + c] : 0.f;
            #pragma unroll
            for (int jj = 0; jj < 6; ++jj) {
                float wv = Ws_[jg * 6 + jj][nn];
                acc[jj] = fmaf(wv, f, acc[jj]);
                if (cl == 0) wsum[jj] += wv;
            }
        }
    }
    __syncthreads();
    if (cl == 0)
        #pragma unroll
        for (int jj = 0; jj < 6; ++jj) swj[jg * 6 + jj] = wsum[jj];
    __syncthreads();
    if (c < 451)
        #pragma unroll
        for (int jj = 0; jj < 6; ++jj) {
            int j = jg * 6 + jj;
            pooled[((size_t)b * Jj + j) * 451 + c] = acc[jj] / (swj[j] + 1e-5f);
        }
}

// ---------------------------------------------------------------------------
extern "C" void kernel_launch(void* const* d_in, const int* in_sizes, int n_in,
                              void* d_out, int out_size) {
    const float* V   = (const float*)d_in[0];
    const float* Wmt = (const float*)d_in[1];
    const int*   sIx = (const int*)d_in[2];
    const float* g1w = (const float*)d_in[3];  const float* g1b = (const float*)d_in[4];
    const float* g2w = (const float*)d_in[5];  const float* g2b = (const float*)d_in[6];
    const float* g3w = (const float*)d_in[7];  const float* g3b = (const float*)d_in[8];
    const float* s1w = (const float*)d_in[9];  const float* s1b = (const float*)d_in[10];
    const float* s2w = (const float*)d_in[11]; const float* s2b = (const float*)d_in[12];
    const float* s3w = (const float*)d_in[13]; const float* s3b = (const float*)d_in[14];
    const float* m1w = (const float*)d_in[15]; const float* m1b = (const float*)d_in[16];
    const float* m2w = (const float*)d_in[17]; const float* m2b = (const float*)d_in[18];
    const float* m3w = (const float*)d_in[19]; const float* m3b = (const float*)d_in[20];
    float* out = (float*)d_out;

    float* S = nullptr; cudaGetSymbolAddress((void**)&S, d_SF);
    int*  KI = nullptr; cudaGetSymbolAddress((void**)&KI, d_SI);

    float* feat   = S + OF_FEAT;
    float* PQ     = S + OF_PQ;
    float* nrm    = S + OF_NORM;
    float* pooled = S + OF_POOL;
    float* joints = S + OF_JNT;
    float* t1     = S + OF_T1;
    float* t2     = S + OF_T2;
    float* wg2 = S + OF_WG2; float* wg3 = S + OF_WG3;
    float* ws1 = S + OF_WS1; float* ws2 = S + OF_WS2; float* ws3 = S + OF_WS3;

    // dynamic smem: knn base(C) = C*68 + 2*16*132 + 64*132 + 192 floats;
    // gemm8 needs 12800 B; merge needs 40960 B.
    const int SM_MERGE = 64 * 4 * KTOP * 2 * 4;                         // 40960
    const int SM_C3   = (3 * 68 + 2 * 3 * 132 + 64 * 132 + 192) * 4;    // 38544
    const int SM_C64  = (64 * 68 + 2 * 16 * 132 + 64 * 132 + 192) * 4;  // 68864
    const int SM_C128 = (128 * 68 + 2 * 16 * 132 + 64 * 132 + 192) * 4; // 86272
    const int SM_K3   = (SM_C3 > SM_MERGE) ? SM_C3 : SM_MERGE;          // 40960
    cudaFuncSetAttribute((const void*)prep_knn3_kernel,
                         cudaFuncAttributeMaxDynamicSharedMemorySize, SM_K3);
    cudaFuncSetAttribute((const void*)knn_gemm_kernel<64>,
                         cudaFuncAttributeMaxDynamicSharedMemorySize, SM_C64);
    cudaFuncSetAttribute((const void*)knn_gemm_kernel<128>,
                         cudaFuncAttributeMaxDynamicSharedMemorySize, SM_C128);

    const int M = Bb * Nn;               // 16384

    // ---- layer 1: fused (prep + copyV + K=3 PQ gemm) || knn<3>
    prep_knn3_kernel<<<KNN_BLKS + PREP_BLKS + COPY_BLKS + GEMM1_BLKS, 256, SM_K3>>>(
        V, g1w, g1b, g2w, g3w, s1w, s2w, s3w, S, feat, PQ, KI);            // 1
    gathermax4_kernel<<<M / 8, 128>>>(PQ, 64, KI, KTOP, Nn, feat + 3, 451, nrm); // 2

    // ---- layer 2: fused knn<64> || gemm2 (both consume feat+3)
    knn_gemm_kernel<64><<<KNN_BLKS + 512, 256, SM_C64>>>(
        feat + 3, 451, nrm, KI, KNN_BLKS,
        wg2, g2b, 128, PQ, 256, M, 256, 64);                               // 3
    gathermax4_kernel<<<M / 4, 128>>>(PQ, 128, KI, KTOP, Nn, feat + 67, 451, nrm); // 4 (ncu)

    // ---- layer 3: fused knn<128> || gemm3 (both consume feat+67)
    knn_gemm_kernel<128><<<KNN_BLKS + 1024, 256, SM_C128>>>(
        feat + 67, 451, nrm, KI, KNN_BLKS,
        wg3, g3b, 256, PQ, 512, M, 512, 128);                              // 5
    gathermax4_kernel<<<M / 2, 128>>>(PQ, 256, KI, KTOP, Nn, feat + 195, 451, nullptr);

    // ---- weighted pooling onto 24 joints
    pool_kernel<<<dim3(8, Bb), 256>>>(Wmt, feat, pooled);

    const int MJ = Bb * Jj;              // 96
    // ---- skeleton edge conv 1 (C=451 -> O=256)
    gemm_kernel<<<dim3(2, 8), 256>>>(pooled, 451, ws1, s1b, 256, PQ, 512, MJ, 512, 451, 0);
    gathermax4_kernel<<<MJ / 2, 128>>>(PQ, 256, sIx, 4, Jj, joints, 448, nullptr);
    // ---- skeleton edge conv 2 (C=256 -> O=128)
    gemm_kernel<<<dim3(2, 4), 256>>>(joints, 448, ws2, s2b, 128, PQ, 256, MJ, 256, 256, 0);
    gathermax4_kernel<<<MJ / 4, 128>>>(PQ, 128, sIx, 4, Jj, joints + 256, 448, nullptr);
    // ---- skeleton edge conv 3 (C=128 -> O=64)
    gemm_kernel<<<dim3(2, 2), 256>>>(joints + 256, 448, ws3, s3b, 64, PQ, 128, MJ, 128, 128, 0);
    gathermax4_kernel<<<MJ / 8, 128>>>(PQ, 64, sIx, 4, Jj, joints + 384, 448, nullptr);

    // ---- joint MLP 448 -> 512 -> 256 -> 3
    gemm_kernel<<<dim3(2, 8), 256>>>(joints, 448, m1w, m1b, 0, t1, 512, MJ, 512, 448, 1);
    gemm_kernel<<<dim3(2, 4), 256>>>(t1, 512, m2w, m2b, 0, t2, 256, MJ, 256, 512, 1);
    gemm_kernel<<<dim3(2, 1), 256>>>(t2, 256, m3w, m3b, 0, out, 3, MJ, 3, 256, 0);
}